// round 16
// baseline (speedup 1.0000x reference)
#include <cuda_runtime.h>
#include <cstdint>
#include <math.h>

#define SEQ   2048
#define BATCH 64
#define INP   256
#define HID   256

typedef unsigned long long ull;

// ---------- packed f32x2 helpers (Blackwell FFMA2 path, PTX-only) ----------
__device__ __forceinline__ void ffma2(ull& d, ull a, ull b) {
    asm("fma.rn.f32x2 %0, %1, %2, %0;" : "+l"(d) : "l"(a), "l"(b));
}
__device__ __forceinline__ ull pk(float a, float b) {
    ull r; asm("mov.b64 %0, {%1, %2};" : "=l"(r) : "f"(a), "f"(b)); return r;
}
__device__ __forceinline__ ull pku(unsigned a, unsigned b) {
    ull r; asm("mov.b64 %0, {%1, %2};" : "=l"(r) : "r"(a), "r"(b)); return r;
}
__device__ __forceinline__ float2 unpk(ull v) {
    float x, y; asm("mov.b64 {%0, %1}, %2;" : "=f"(x), "=f"(y) : "l"(v));
    return make_float2(x, y);
}
__device__ __forceinline__ unsigned smem_u32(const void* p) {
    unsigned a;
    asm("{ .reg .u64 t; cvta.to.shared.u64 t, %1; cvt.u32.u64 %0, t; }"
        : "=r"(a) : "l"(p));
    return a;
}
__device__ __forceinline__ unsigned mapa_peer(unsigned local_addr, unsigned peer) {
    unsigned r;
    asm("mapa.shared::cluster.u32 %0, %1, %2;" : "=r"(r) : "r"(local_addr), "r"(peer));
    return r;
}
// Branch-free tanh: 1 - 2/(e^{2x}+1). ex2/rcp approx, abs err ~1e-7.
__device__ __forceinline__ float fast_tanh(float x) {
    float e;
    asm("ex2.approx.ftz.f32 %0, %1;" : "=f"(e) : "f"(x * 2.8853900817779268f));
    float r;
    asm("rcp.approx.ftz.f32 %0, %1;" : "=f"(r) : "f"(e + 1.0f));
    return fmaf(-2.0f, r, 1.0f);
}

// =====================================================================
// Fused scan, v14 = R14 scan + in-loop xp computation (gemm deleted).
// Cluster {2b,2b+1}; rank r finalizes rows [128r,+128) over all 256 k.
// 512 threads: jj=tid&127 (row), g=tid>>7:
//   g0/g1: local-k h matvec; g3: remote-k (poll pairs); g2: remote-k
//   + FINALIZER (polls 3 partial pairs, tanh, sends, stores).
// NEW: every thread also computes xp_t partial for its row over x
//   window [64g,+64): W_ih staged in smem ([chunk][row] layout,
//   conflict-free LDS.128), x_t staged in a 6-slot smem ring
//   prefetched 5 steps ahead by threads 0-63. The xp partial rides in
//   the same {f32,seq} pair the thread already publishes — zero new
//   synchronization, work lands in the transit-wait idle cycles.
// Remote h / partials: {f32,seq} u64 pairs, parity double-buffered,
// seq-validated, NO fences/mbarriers. One bar.sync per step.
// =====================================================================
#define WIH_BYTES   131072              // 8192 float4
#define PAIR_OFF    131072              // pairbuf [2][128] ull
#define PPAIR_OFF   133120              // ppair [2][3][128] ull
#define HBUF_OFF    139264              // hbuf [2][128] float
#define XSM_OFF     140288              // xsm [6][256] float
#define SCAN_SMEM   146432

__global__ __launch_bounds__(512, 1) __cluster_dims__(2, 1, 1)
void rnn_scan_fused_kernel(
    const float* __restrict__ x,    // [SEQ][BATCH][INP]
    const float* __restrict__ Whh,  // [HID][HID]
    const float* __restrict__ Wih,  // [HID][INP]
    const float* __restrict__ bih,  // [HID]
    const float* __restrict__ bhh,  // [HID]
    float* __restrict__ out)        // [SEQ][BATCH][HID]
{
    extern __shared__ char smem_raw[];
    float4* wih4   = (float4*)smem_raw;                   // [c*128 + jj]
    ull*    pairbuf= (ull*)(smem_raw + PAIR_OFF);         // [par*128 + jj]
    ull*    ppair  = (ull*)(smem_raw + PPAIR_OFF);        // [par*384 + src*128 + jj]
    float*  hbuf   = (float*)(smem_raw + HBUF_OFF);       // [par*128 + jj]
    float*  xsm    = (float*)(smem_raw + XSM_OFF);        // [slot*256 + col]

    const int bidx = blockIdx.x;
    const int b    = bidx >> 1;
    const int r    = bidx & 1;             // cluster rank
    const int tid  = threadIdx.x;
    const int jj   = tid & 127;            // row within my half
    const int g    = tid >> 7;             // group / window index
    const int lane = tid & 31;
    const int j    = 128 * r + jj;         // my (local) global row

    const int koff = (g < 2) ? (128 * r + 64 * g)
                             : (128 * (1 - r) + 64 * (g - 2));

    // ---- register-resident W_hh: row j, k in [koff,+64) ----
    ull wreg[32];
    {
        const float* wrow = Whh + (size_t)j * HID + koff;
        #pragma unroll
        for (int p = 0; p < 32; ++p)
            wreg[p] = *(const ull*)(wrow + 2 * p);
    }

    // ---- stage W_ih into smem: wih4[c*128+jj] = Wih[128r+jj][4c..4c+3] ----
    for (int i = tid; i < 8192; i += 512) {
        int c  = i >> 7;
        int rr = i & 127;
        wih4[i] = *(const float4*)(Wih + (size_t)(128 * r + rr) * INP + 4 * c);
    }

    // ---- x ring prologue: slots 0..4 = x[0..4]; regs hold x[5], x[6] ----
    float4 xrA = make_float4(0.f, 0.f, 0.f, 0.f);
    float4 xrB = make_float4(0.f, 0.f, 0.f, 0.f);
    if (tid < 64) {
        #pragma unroll
        for (int s = 0; s < 5; ++s)
            *(float4*)&xsm[s * 256 + tid * 4] =
                __ldcg((const float4*)(x + ((size_t)s * BATCH + b) * INP) + tid);
        xrA = __ldcg((const float4*)(x + ((size_t)5 * BATCH + b) * INP) + tid);
        xrB = __ldcg((const float4*)(x + ((size_t)6 * BATCH + b) * INP) + tid);
    }

    // ---- other init ----
    if (tid < 256) hbuf[tid] = 0.f;
    if (tid < 256) pairbuf[tid] = 0ull;        // seq=0 matches t=0 poll
    for (int i = tid; i < 768; i += 512) ppair[i] = 0ull;

    float bias = 0.f;
    if (g == 2) bias = bih[j] + bhh[j];

    __syncthreads();
    asm volatile("barrier.cluster.arrive.aligned;" ::: "memory");
    asm volatile("barrier.cluster.wait.aligned;"   ::: "memory");

    const unsigned peer      = (unsigned)(r ^ 1);
    const unsigned pair_l    = smem_u32(pairbuf);
    const unsigned ppair_l   = smem_u32(ppair);
    const unsigned peer_pair = mapa_peer(pair_l, peer);

    const size_t stride = (size_t)BATCH * HID;
    float* col = out + (size_t)b * HID + j;

    for (int t = 0; t < SEQ; ++t) {
        const unsigned sp = (unsigned)(t & 1);   // publish parity
        const unsigned rp = sp ^ 1u;             // read parity
        const unsigned T1 = (unsigned)(t + 1);

        // ---- x ring staging (threads 0-63; off the critical path) ----
        if (tid < 64) {
            if (t + 5 < SEQ)
                *(float4*)&xsm[((t + 5) % 6) * 256 + tid * 4] = xrA;
            xrA = xrB;
            if (t + 7 < SEQ)
                xrB = __ldcg((const float4*)(x + ((size_t)(t + 7) * BATCH + b) * INP) + tid);
        }

        // ---- xp partial: row j over x window [64g,+64) (independent) ----
        float part;
        {
            const float4* xw = (const float4*)&xsm[(t % 6) * 256 + 64 * g];
            const float4* ww = &wih4[(g * 16) * 128 + jj];
            ull b0 = 0ull, b1 = 0ull;
            #pragma unroll
            for (int q = 0; q < 16; ++q) {
                float4 wv = ww[q * 128];     // conflict-free (lane-consecutive)
                float4 xv = xw[q];           // broadcast
                ffma2(b0, pk(wv.x, wv.y), pk(xv.x, xv.y));
                ffma2(b1, pk(wv.z, wv.w), pk(xv.z, xv.w));
            }
            float2 u0 = unpk(b0), u1 = unpk(b1);
            part = (u0.x + u0.y) + (u1.x + u1.y);
        }

        // ---- h matvec partial over my 64 k-values ----
        ull a0 = 0ull, a1 = 0ull, a2 = 0ull, a3 = 0ull;
        if (g < 2) {
            const ulonglong2* h2 =
                (const ulonglong2*)(hbuf + rp * 128 + 64 * g);
            #pragma unroll
            for (int q = 0; q < 16; ++q) {
                ulonglong2 h = h2[q];
                if (q & 1) { ffma2(a2, wreg[2 * q],     h.x);
                             ffma2(a3, wreg[2 * q + 1], h.y); }
                else       { ffma2(a0, wreg[2 * q],     h.x);
                             ffma2(a1, wreg[2 * q + 1], h.y); }
            }
        } else {
            // peer h: warp-collective seqno validation, then bulk pair reads
            const unsigned base = pair_l + rp * 1024u
                                         + (unsigned)(g - 2) * 512u;
            const unsigned aA = base + (unsigned)lane * 8u;
            const unsigned aB = aA + 256u;
            const unsigned T  = (unsigned)t;
            unsigned ok;
            do {
                ull p1, p2;
                asm volatile("ld.volatile.shared.u64 %0, [%1];"
                             : "=l"(p1) : "r"(aA) : "memory");
                asm volatile("ld.volatile.shared.u64 %0, [%1];"
                             : "=l"(p2) : "r"(aB) : "memory");
                ok = ((unsigned)(p1 >> 32) == T) & ((unsigned)(p2 >> 32) == T);
            } while (__all_sync(0xFFFFFFFFu, ok) == 0);

            const uint4* pq = (const uint4*)((const char*)pairbuf
                               + (int)rp * 1024 + (g - 2) * 512);
            #pragma unroll
            for (int q = 0; q < 16; ++q) {
                uint4 vA = pq[2 * q];        // {h0,s0,h1,s1}
                uint4 vB = pq[2 * q + 1];
                if (q & 1) { ffma2(a2, wreg[2 * q],     pku(vA.x, vA.z));
                             ffma2(a3, wreg[2 * q + 1], pku(vB.x, vB.z)); }
                else       { ffma2(a0, wreg[2 * q],     pku(vA.x, vA.z));
                             ffma2(a1, wreg[2 * q + 1], pku(vB.x, vB.z)); }
            }
        }
        float2 s0 = unpk(a0), s1 = unpk(a1), s2 = unpk(a2), s3 = unpk(a3);
        part += ((s0.x + s0.y) + (s1.x + s1.y))
              + ((s2.x + s2.y) + (s3.x + s3.y));

        if (g != 2) {
            // publish combined partial {xp+h, t+1}; src: g0->0, g1->1, g3->2
            const int src = (g < 2) ? g : 2;
            ull pv = pku(__float_as_uint(part), T1);
            unsigned pa = ppair_l + sp * 3072u
                                  + (unsigned)src * 1024u
                                  + (unsigned)jj * 8u;
            asm volatile("st.volatile.shared.u64 [%0], %1;"
                         :: "r"(pa), "l"(pv) : "memory");
        } else {
            // ---- g2 finalizes: poll 3 partial pairs (all ~ready) ----
            const unsigned pa = ppair_l + sp * 3072u + (unsigned)jj * 8u;
            ull v1, v2, v3;
            unsigned ok;
            do {
                asm volatile("ld.volatile.shared.u64 %0, [%1];"
                             : "=l"(v1) : "r"(pa) : "memory");
                asm volatile("ld.volatile.shared.u64 %0, [%1];"
                             : "=l"(v2) : "r"(pa + 1024u) : "memory");
                asm volatile("ld.volatile.shared.u64 %0, [%1];"
                             : "=l"(v3) : "r"(pa + 2048u) : "memory");
                ok = ((unsigned)(v1 >> 32) == T1)
                   & ((unsigned)(v2 >> 32) == T1)
                   & ((unsigned)(v3 >> 32) == T1);
            } while (!ok);

            float sum = part
                      + (__uint_as_float((unsigned)v1)
                      +  __uint_as_float((unsigned)v2))
                      +  __uint_as_float((unsigned)v3);
            float val = fast_tanh(bias + sum);

            // 1) remote h pair FIRST (starts transit earliest)
            if (t + 1 < SEQ) {
                ull hv = pku(__float_as_uint(val), T1);
                asm volatile("st.shared::cluster.u64 [%0], %1;"
                             :: "r"(peer_pair + sp * 1024u
                                              + (unsigned)jj * 8u),
                                "l"(hv) : "memory");
            }
            // 2) local h (ordered by the bar.sync below)
            hbuf[sp * 128 + jj] = val;
            // 3) output
            col[(size_t)t * stride] = val;
        }

        __syncthreads();   // single per-step barrier
    }

    asm volatile("barrier.cluster.arrive.aligned;" ::: "memory");
    asm volatile("barrier.cluster.wait.aligned;"   ::: "memory");
}

// =====================================================================
extern "C" void kernel_launch(void* const* d_in, const int* in_sizes, int n_in,
                              void* d_out, int out_size) {
    const float* x   = (const float*)d_in[0];  // [SEQ][BATCH][INP]
    const float* Wih = (const float*)d_in[1];  // [HID][INP]
    const float* Whh = (const float*)d_in[2];  // [HID][HID]
    const float* bih = (const float*)d_in[3];  // [HID]
    const float* bhh = (const float*)d_in[4];  // [HID]
    float* out = (float*)d_out;                // [SEQ][BATCH][HID]

    static int smem_set = 0;
    if (!smem_set) {
        cudaFuncSetAttribute(rnn_scan_fused_kernel,
                             cudaFuncAttributeMaxDynamicSharedMemorySize,
                             SCAN_SMEM);
        smem_set = 1;
    }

    rnn_scan_fused_kernel<<<2 * BATCH, 512, SCAN_SMEM>>>(
        x, Whh, Wih, bih, bhh, out);
}

// round 17
// speedup vs baseline: 1.0275x; 1.0275x over previous
#include <cuda_runtime.h>
#include <cstdint>
#include <math.h>

#define SEQ   2048
#define BATCH 64
#define INP   256
#define HID   256

typedef unsigned long long ull;

// ---------- packed f32x2 helpers (Blackwell FFMA2 path, PTX-only) ----------
__device__ __forceinline__ void ffma2(ull& d, ull a, ull b) {
    asm("fma.rn.f32x2 %0, %1, %2, %0;" : "+l"(d) : "l"(a), "l"(b));
}
__device__ __forceinline__ ull pk(float a, float b) {
    ull r; asm("mov.b64 %0, {%1, %2};" : "=l"(r) : "f"(a), "f"(b)); return r;
}
__device__ __forceinline__ ull pku(unsigned a, unsigned b) {
    ull r; asm("mov.b64 %0, {%1, %2};" : "=l"(r) : "r"(a), "r"(b)); return r;
}
__device__ __forceinline__ float2 unpk(ull v) {
    float x, y; asm("mov.b64 {%0, %1}, %2;" : "=f"(x), "=f"(y) : "l"(v));
    return make_float2(x, y);
}
__device__ __forceinline__ unsigned smem_u32(const void* p) {
    unsigned a;
    asm("{ .reg .u64 t; cvta.to.shared.u64 t, %1; cvt.u32.u64 %0, t; }"
        : "=r"(a) : "l"(p));
    return a;
}
__device__ __forceinline__ unsigned mapa_peer(unsigned local_addr, unsigned peer) {
    unsigned r;
    asm("mapa.shared::cluster.u32 %0, %1, %2;" : "=r"(r) : "r"(local_addr), "r"(peer));
    return r;
}
// Branch-free tanh: 1 - 2/(e^{2x}+1). ex2/rcp approx, abs err ~1e-7.
__device__ __forceinline__ float fast_tanh(float x) {
    float e;
    asm("ex2.approx.ftz.f32 %0, %1;" : "=f"(e) : "f"(x * 2.8853900817779268f));
    float r;
    asm("rcp.approx.ftz.f32 %0, %1;" : "=f"(r) : "f"(e + 1.0f));
    return fmaf(-2.0f, r, 1.0f);
}

// =====================================================================
// Phase 1 v2: xp[t,b,h] = x[t,b]·W_ih[h] + b_ih[h] + b_hh[h]
// One CTA per t, 256 threads, issue-diet inner loop:
//   Xd: duplicated-packed x (ull {x,x}) -> 4 broadcast LDS.128/k, no movs
//   Wd: h-pair-packed W (ull {w_h,w_h+1}) -> 2 lane-consecutive LDS.128/k
//   38 issue slots per 32 ffma2 (was ~50).
// Thread (tm=tid>>5, tn=lane): rows 8tm..+8, h in {4tn..+4, 128+4tn..+4}.
// =====================================================================
#define XDP 66                      // Xd row stride (ull)
#define WDP 130                     // Wd row stride (ull)
#define GEMM_SMEM ((32 * XDP + 32 * WDP) * 8)   // 50176 B

__global__ __launch_bounds__(256, 2) void xp_gemm_kernel(
    const float* __restrict__ x,
    const float* __restrict__ Wih,
    const float* __restrict__ bih,
    const float* __restrict__ bhh,
    float* __restrict__ out)
{
    extern __shared__ ull gsm[];
    ull* Xd = gsm;                  // [k][m]  32 x XDP
    ull* Wd = gsm + 32 * XDP;       // [k][h2] 32 x WDP

    const int t   = blockIdx.x;
    const int tid = threadIdx.x;
    const int tn  = tid & 31;
    const int tm  = tid >> 5;
    const int m0  = tm * 8;

    const float* xt = x + (size_t)t * BATCH * INP;

    ull acc[8][4];
    #pragma unroll
    for (int u = 0; u < 8; ++u)
        #pragma unroll
        for (int v = 0; v < 4; ++v) acc[u][v] = 0ull;

    for (int kc = 0; kc < INP; kc += 32) {
        // ---- stage Xd: duplicated-packed x, [k][m] ----
        #pragma unroll
        for (int r2 = 0; r2 < 2; ++r2) {
            int idx = tid + 256 * r2;          // 0..511
            int m   = idx >> 3;                // 0..63
            int k4  = (idx & 7) * 4;           // 0..28
            float4 v = *(const float4*)(xt + (size_t)m * INP + kc + k4);
            Xd[(k4 + 0) * XDP + m] = pk(v.x, v.x);
            Xd[(k4 + 1) * XDP + m] = pk(v.y, v.y);
            Xd[(k4 + 2) * XDP + m] = pk(v.z, v.z);
            Xd[(k4 + 3) * XDP + m] = pk(v.w, v.w);
        }
        // ---- stage Wd: h-pair-packed W, [k][h2] ----
        #pragma unroll
        for (int r2 = 0; r2 < 4; ++r2) {
            int idx = tid + 256 * r2;          // 0..1023
            int h2  = idx >> 3;                // 0..127
            int k4  = (idx & 7) * 4;
            float4 wa = *(const float4*)(Wih + (size_t)(2 * h2)     * INP + kc + k4);
            float4 wb = *(const float4*)(Wih + (size_t)(2 * h2 + 1) * INP + kc + k4);
            Wd[(k4 + 0) * WDP + h2] = pk(wa.x, wb.x);
            Wd[(k4 + 1) * WDP + h2] = pk(wa.y, wb.y);
            Wd[(k4 + 2) * WDP + h2] = pk(wa.z, wb.z);
            Wd[(k4 + 3) * WDP + h2] = pk(wa.w, wb.w);
        }
        __syncthreads();

        #pragma unroll
        for (int k = 0; k < 32; ++k) {
            const ulonglong2* xp2 = (const ulonglong2*)&Xd[k * XDP + m0];
            ulonglong2 xA = xp2[0];            // rows m0+0, m0+1 (broadcast)
            ulonglong2 xB = xp2[1];
            ulonglong2 xC = xp2[2];
            ulonglong2 xD = xp2[3];
            ulonglong2 w1 = *(const ulonglong2*)&Wd[k * WDP + 2 * tn];       // h 4tn..+3
            ulonglong2 w2 = *(const ulonglong2*)&Wd[k * WDP + 64 + 2 * tn];  // h 128+4tn..+3

            ull ap[8] = { xA.x, xA.y, xB.x, xB.y, xC.x, xC.y, xD.x, xD.y };
            #pragma unroll
            for (int u = 0; u < 8; ++u) {
                ffma2(acc[u][0], w1.x, ap[u]);
                ffma2(acc[u][1], w1.y, ap[u]);
                ffma2(acc[u][2], w2.x, ap[u]);
                ffma2(acc[u][3], w2.y, ap[u]);
            }
        }
        __syncthreads();
    }

    // epilogue: bias + vectorized store (float4 per h-quad)
    float4 biA, biB;
    {
        float4 a1 = *(const float4*)(bih + 4 * tn);
        float4 a2 = *(const float4*)(bhh + 4 * tn);
        float4 b1 = *(const float4*)(bih + 128 + 4 * tn);
        float4 b2 = *(const float4*)(bhh + 128 + 4 * tn);
        biA = make_float4(a1.x + a2.x, a1.y + a2.y, a1.z + a2.z, a1.w + a2.w);
        biB = make_float4(b1.x + b2.x, b1.y + b2.y, b1.z + b2.z, b1.w + b2.w);
    }
    float* ot = out + (size_t)t * BATCH * HID;
    #pragma unroll
    for (int u = 0; u < 8; ++u) {
        float* row = ot + (size_t)(m0 + u) * HID;
        float2 p0 = unpk(acc[u][0]), p1 = unpk(acc[u][1]);
        float2 p2 = unpk(acc[u][2]), p3 = unpk(acc[u][3]);
        *(float4*)(row + 4 * tn) =
            make_float4(p0.x + biA.x, p0.y + biA.y, p1.x + biA.z, p1.y + biA.w);
        *(float4*)(row + 128 + 4 * tn) =
            make_float4(p2.x + biB.x, p2.y + biB.y, p3.x + biB.z, p3.y + biB.w);
    }
}

// =====================================================================
// Phase 2: serial scan — R14 (v12) VERBATIM, the proven best (1165 cyc/step).
// Cluster {2b,2b+1}; rank r finalizes rows [128r,+128) over all 256 k.
//   g0/g1: local k matvec -> partial pair;  g3: remote k -> partial pair;
//   g2: remote k + FINALIZER (poll 3 pairs, tanh, send, store).
// {f32,seq} u64 pairs, parity double-buffered, no fences/mbarriers.
// One __syncthreads per step.
// =====================================================================
__global__ __launch_bounds__(512, 1) __cluster_dims__(2, 1, 1)
void rnn_scan_kernel(
    const float* __restrict__ Whh,  // [HID][HID]
    float* __restrict__ out)        // in: xp, out: h   [SEQ][BATCH][HID]
{
    __shared__ float hbuf[2][128];                 // local h by parity
    __shared__ alignas(16) ull pairbuf[2][128];    // peer h pairs by parity
    __shared__ alignas(16) ull ppair[2][3][128];   // partial pairs [par][src][jj]

    const int bidx = blockIdx.x;
    const int b    = bidx >> 1;
    const int r    = bidx & 1;             // cluster rank
    const int tid  = threadIdx.x;
    const int jj   = tid & 127;            // row within my half
    const int g    = tid >> 7;             // k-window group
    const int lane = tid & 31;
    const int j    = 128 * r + jj;         // global row

    const int koff = (g < 2) ? (128 * r + 64 * g)
                             : (128 * (1 - r) + 64 * (g - 2));

    // ---- register-resident W: W_hh[j][koff + 0..63] ----
    ull wreg[32];
    {
        const float* wrow = Whh + (size_t)j * HID + koff;
        #pragma unroll
        for (int p = 0; p < 32; ++p)
            wreg[p] = *(const ull*)(wrow + 2 * p);
    }

    // ---- init smem ----
    if (tid < 256) ((float*)hbuf)[tid] = 0.f;
    if (tid < 256) ((ull*)pairbuf)[tid] = 0ull;    // seq=0 matches t=0 poll
    for (int i = tid; i < 768; i += 512) ((ull*)ppair)[i] = 0ull;
    __syncthreads();
    asm volatile("barrier.cluster.arrive.aligned;" ::: "memory");
    asm volatile("barrier.cluster.wait.aligned;"   ::: "memory");

    const unsigned peer      = (unsigned)(r ^ 1);
    const unsigned pair_l    = smem_u32(pairbuf);
    const unsigned ppair_l   = smem_u32(ppair);
    const unsigned peer_pair = mapa_peer(pair_l, peer);

    const size_t stride = (size_t)BATCH * HID;
    float* col = out + (size_t)b * HID + j;

    // xp prefetch queue, depth 2 (g2 = finalizer holds it)
    float xq0 = 0.f, xq1 = 0.f;
    if (g == 2) {
        xq0 = __ldcg(col);
        xq1 = __ldcg(col + stride);
    }

    for (int t = 0; t < SEQ; ++t) {
        const unsigned sp = (unsigned)(t & 1);   // publish parity
        const unsigned rp = sp ^ 1u;             // read parity
        const unsigned T1 = (unsigned)(t + 1);

        // g2: hoist next xp load above everything (independent)
        float xq2 = 0.f;
        if (g == 2 && t + 2 < SEQ)
            xq2 = __ldcg(col + (size_t)(t + 2) * stride);

        // ---- matvec partial over my 64 k-values ----
        ull a0 = 0ull, a1 = 0ull, a2 = 0ull, a3 = 0ull;
        if (g < 2) {
            const ulonglong2* h2 =
                (const ulonglong2*)&hbuf[rp][64 * g];
            #pragma unroll
            for (int q = 0; q < 16; ++q) {
                ulonglong2 h = h2[q];
                if (q & 1) { ffma2(a2, wreg[2 * q],     h.x);
                             ffma2(a3, wreg[2 * q + 1], h.y); }
                else       { ffma2(a0, wreg[2 * q],     h.x);
                             ffma2(a1, wreg[2 * q + 1], h.y); }
            }
        } else {
            // peer h: warp-collective seqno validation, then bulk pair reads
            const unsigned base = pair_l + rp * 1024u
                                         + (unsigned)(g - 2) * 512u;
            const unsigned aA = base + (unsigned)lane * 8u;
            const unsigned aB = aA + 256u;
            const unsigned T  = (unsigned)t;
            unsigned ok;
            do {
                ull p1, p2;
                asm volatile("ld.volatile.shared.u64 %0, [%1];"
                             : "=l"(p1) : "r"(aA) : "memory");
                asm volatile("ld.volatile.shared.u64 %0, [%1];"
                             : "=l"(p2) : "r"(aB) : "memory");
                ok = ((unsigned)(p1 >> 32) == T) & ((unsigned)(p2 >> 32) == T);
            } while (__all_sync(0xFFFFFFFFu, ok) == 0);

            const uint4* pq = (const uint4*)((const char*)pairbuf
                               + (int)rp * 1024 + (g - 2) * 512);
            #pragma unroll
            for (int q = 0; q < 16; ++q) {
                uint4 vA = pq[2 * q];        // {h0,s0,h1,s1}
                uint4 vB = pq[2 * q + 1];
                if (q & 1) { ffma2(a2, wreg[2 * q],     pku(vA.x, vA.z));
                             ffma2(a3, wreg[2 * q + 1], pku(vB.x, vB.z)); }
                else       { ffma2(a0, wreg[2 * q],     pku(vA.x, vA.z));
                             ffma2(a1, wreg[2 * q + 1], pku(vB.x, vB.z)); }
            }
        }
        float2 s0 = unpk(a0), s1 = unpk(a1), s2 = unpk(a2), s3 = unpk(a3);
        float part = ((s0.x + s0.y) + (s1.x + s1.y))
                   + ((s2.x + s2.y) + (s3.x + s3.y));

        if (g != 2) {
            // publish partial pair {part, t+1}; src idx: g0->0, g1->1, g3->2
            const int src = (g < 2) ? g : 2;
            ull pv = pku(__float_as_uint(part), T1);
            unsigned pa = ppair_l + sp * 3072u
                                  + (unsigned)src * 1024u
                                  + (unsigned)jj * 8u;
            asm volatile("st.volatile.shared.u64 [%0], %1;"
                         :: "r"(pa), "l"(pv) : "memory");
        } else {
            // ---- g2 finalizes: poll 3 partial pairs (all ~ready) ----
            const unsigned pa = ppair_l + sp * 3072u + (unsigned)jj * 8u;
            ull v1, v2, v3;
            unsigned ok;
            do {
                asm volatile("ld.volatile.shared.u64 %0, [%1];"
                             : "=l"(v1) : "r"(pa) : "memory");
                asm volatile("ld.volatile.shared.u64 %0, [%1];"
                             : "=l"(v2) : "r"(pa + 1024u) : "memory");
                asm volatile("ld.volatile.shared.u64 %0, [%1];"
                             : "=l"(v3) : "r"(pa + 2048u) : "memory");
                ok = ((unsigned)(v1 >> 32) == T1)
                   & ((unsigned)(v2 >> 32) == T1)
                   & ((unsigned)(v3 >> 32) == T1);
            } while (!ok);

            float sum = part
                      + (__uint_as_float((unsigned)v1)
                      +  __uint_as_float((unsigned)v2))
                      +  __uint_as_float((unsigned)v3);
            float val = fast_tanh(xq0 + sum);

            // 1) remote h pair FIRST (starts transit earliest)
            if (t + 1 < SEQ) {
                ull hv = pku(__float_as_uint(val), T1);
                asm volatile("st.shared::cluster.u64 [%0], %1;"
                             :: "r"(peer_pair + sp * 1024u
                                              + (unsigned)jj * 8u),
                                "l"(hv) : "memory");
            }
            // 2) local h (ordered by the bar.sync below)
            hbuf[sp][jj] = val;
            // 3) output
            col[(size_t)t * stride] = val;
            // 4) advance xp queue
            xq0 = xq1;
            xq1 = xq2;
        }

        __syncthreads();   // single per-step barrier: hbuf/slot-reuse order
    }

    asm volatile("barrier.cluster.arrive.aligned;" ::: "memory");
    asm volatile("barrier.cluster.wait.aligned;"   ::: "memory");
}

// =====================================================================
extern "C" void kernel_launch(void* const* d_in, const int* in_sizes, int n_in,
                              void* d_out, int out_size) {
    const float* x   = (const float*)d_in[0];  // [SEQ][BATCH][INP]
    const float* Wih = (const float*)d_in[1];  // [HID][INP]
    const float* Whh = (const float*)d_in[2];  // [HID][HID]
    const float* bih = (const float*)d_in[3];  // [HID]
    const float* bhh = (const float*)d_in[4];  // [HID]
    float* out = (float*)d_out;                // [SEQ][BATCH][HID]

    static int smem_set = 0;
    if (!smem_set) {
        cudaFuncSetAttribute(xp_gemm_kernel,
                             cudaFuncAttributeMaxDynamicSharedMemorySize,
                             GEMM_SMEM);
        smem_set = 1;
    }

    xp_gemm_kernel<<<SEQ, 256, GEMM_SMEM>>>(x, Wih, bih, bhh, out);
    rnn_scan_kernel<<<2 * BATCH, 512>>>(Whh, out);
}